// round 3
// baseline (speedup 1.0000x reference)
#include <cuda_runtime.h>
#include <cstdint>

// ---------------------------------------------------------------------------
// Problem constants
// ---------------------------------------------------------------------------
#define NDET   128
#define HWPIX  661504            // 608 * 1088
#define HW4    (HWPIX / 4)       // float4 per mask
#define NCHUNK (HWPIX / 128)     // 5168 K-chunks of 128 pixels
#define GRAMN  (NDET * NDET)
#define GRID   148

#define MASK_SCORE_THRESH 0.5f
#define MIN_MASK_PIXELS   20.0f
#define IOMIN_THRESH      0.9f
#define IOMAX_THRESH      0.5f
#define HIGH_SCORE_THRESH 0.5f
#define VIS_THRESH        0.1f
#define PED_LABEL         1

// Row stride of the s8 smem tile in bytes (128 data + 16 pad -> conflict-free
// for ldmatrix: 8 consecutive rows hit distinct 16B bank groups).
#define TPITCH 144

// Global scratch: 128x128 s32 Gram (intersection counts; diagonal = areas)
__device__ int d_igram[GRAMN];

// ---------------------------------------------------------------------------
// PTX helpers (portable sm_80+ tensor path)
// ---------------------------------------------------------------------------
__device__ __forceinline__ uint32_t smem_u32(const void* p) {
    uint32_t a;
    asm("{ .reg .u64 t; cvta.to.shared.u64 t, %1; cvt.u32.u64 %0, t; }"
        : "=r"(a) : "l"(p));
    return a;
}

#define LDSM_X4(r0, r1, r2, r3, addr)                                      \
    asm volatile("ldmatrix.sync.aligned.m8n8.x4.shared.b16 "               \
                 "{%0,%1,%2,%3}, [%4];"                                    \
                 : "=r"(r0), "=r"(r1), "=r"(r2), "=r"(r3) : "r"(addr))

#define IMMA16832(c, a0, a1, a2, a3, b0, b1)                               \
    asm volatile("mma.sync.aligned.m16n8k32.row.col.s32.s8.s8.s32 "        \
                 "{%0,%1,%2,%3}, {%4,%5,%6,%7}, {%8,%9}, {%0,%1,%2,%3};"   \
                 : "+r"((c)[0]), "+r"((c)[1]), "+r"((c)[2]), "+r"((c)[3])  \
                 : "r"(a0), "r"(a1), "r"(a2), "r"(a3), "r"(b0), "r"(b1))

// ---------------------------------------------------------------------------
// Kernel 0: zero the gram accumulator
// ---------------------------------------------------------------------------
__global__ void zero_gram_kernel() {
    int i = blockIdx.x * blockDim.x + threadIdx.x;
    if (i < GRAMN) d_igram[i] = 0;
}

// ---------------------------------------------------------------------------
// Kernel 1: fused binarize + Gram.
// 148 persistent CTAs x 256 threads. Per 128-pixel chunk:
//   - 8 warps load 128x128 fp32 (warp w -> rows 16w..16w+15), binarize to
//     packed s8 {0,1} in registers (prefetched one chunk ahead),
//   - store to 128x144B smem tile,
//   - 8 warps in a 4x2 grid each compute a 32x64 tile of D += T*T^T via
//     ldmatrix + IMMA m16n8k32, s32 accumulators in registers.
// Epilogue: atomic reduce into d_igram.
// ---------------------------------------------------------------------------
__global__ void __launch_bounds__(256, 1)
gram_kernel(const float* __restrict__ masks) {
    __shared__ __align__(16) unsigned char tile[NDET * TPITCH];

    const int tid = threadIdx.x;
    const int w   = tid >> 5;
    const int l   = tid & 31;

    const uint32_t tbase = smem_u32(tile);

    // ldmatrix lane addressing
    const uint32_t lrow  = (uint32_t)(l & 15);
    const uint32_t lhalf = (uint32_t)((l >> 4) * 16);

    // mma tile assignment: 4x2 warp grid -> 32 rows x 64 cols each
    const int mrow0 = 32 * (w >> 1);
    const int ncol0 = 64 * (w & 1);

    int acc[2][8][4];
#pragma unroll
    for (int mt = 0; mt < 2; mt++)
#pragma unroll
        for (int nt = 0; nt < 8; nt++)
#pragma unroll
            for (int e = 0; e < 4; e++) acc[mt][nt][e] = 0;

    // load assignment: warp w loads rows 16w..16w+15, lane l -> float4 #l of
    // the 32 float4 covering the chunk's 128 pixels in that row.
    const float4* m4 = (const float4*)masks;
    const size_t  row_base = (size_t)(16 * w) * HW4 + l;

    uint32_t pk[16];

    // prefetch chunk 0
    int k = blockIdx.x;
    if (k < NCHUNK) {
        const float4* p = m4 + row_base + (size_t)k * 32;
        float4 v[16];
#pragma unroll
        for (int r = 0; r < 16; r++) v[r] = p[(size_t)r * HW4];
#pragma unroll
        for (int r = 0; r < 16; r++) {
            pk[r] = (v[r].x > MASK_SCORE_THRESH ? 0x01u       : 0u)
                  | (v[r].y > MASK_SCORE_THRESH ? 0x0100u     : 0u)
                  | (v[r].z > MASK_SCORE_THRESH ? 0x010000u   : 0u)
                  | (v[r].w > MASK_SCORE_THRESH ? 0x01000000u : 0u);
        }
    }

    for (; k < NCHUNK; k += GRID) {
        __syncthreads();   // previous chunk's smem reads are done

        // store binarized tile: warp w rows 16w.., lane l bytes 4l..4l+3
#pragma unroll
        for (int r = 0; r < 16; r++) {
            uint32_t off = (uint32_t)(16 * w + r) * TPITCH + (uint32_t)(4 * l);
            *(uint32_t*)(tile + off) = pk[r];
        }

        // prefetch next chunk (overlaps the MMA phase below)
        int kn = k + GRID;
        if (kn < NCHUNK) {
            const float4* p = m4 + row_base + (size_t)kn * 32;
            float4 v[16];
#pragma unroll
            for (int r = 0; r < 16; r++) v[r] = p[(size_t)r * HW4];
#pragma unroll
            for (int r = 0; r < 16; r++) {
                pk[r] = (v[r].x > MASK_SCORE_THRESH ? 0x01u       : 0u)
                      | (v[r].y > MASK_SCORE_THRESH ? 0x0100u     : 0u)
                      | (v[r].z > MASK_SCORE_THRESH ? 0x010000u   : 0u)
                      | (v[r].w > MASK_SCORE_THRESH ? 0x01000000u : 0u);
            }
        }

        __syncthreads();   // tile ready

        // ---- MMA phase: 4 k32-steps ----
#pragma unroll
        for (int s = 0; s < 4; s++) {
            const uint32_t kb = (uint32_t)(32 * s) + lhalf;

            uint32_t a0, a1, a2, a3, a4, a5, a6, a7;
            uint32_t aaddr = tbase + (uint32_t)(mrow0 + lrow) * TPITCH + kb;
            LDSM_X4(a0, a1, a2, a3, aaddr);
            LDSM_X4(a4, a5, a6, a7, aaddr + 16u * TPITCH);

#pragma unroll
            for (int g = 0; g < 4; g++) {
                uint32_t b0, b1, b2, b3;
                uint32_t baddr = tbase +
                    (uint32_t)(ncol0 + 16 * g + lrow) * TPITCH + kb;
                LDSM_X4(b0, b1, b2, b3, baddr);

                IMMA16832(acc[0][2 * g],     a0, a1, a2, a3, b0, b2);
                IMMA16832(acc[0][2 * g + 1], a0, a1, a2, a3, b1, b3);
                IMMA16832(acc[1][2 * g],     a4, a5, a6, a7, b0, b2);
                IMMA16832(acc[1][2 * g + 1], a4, a5, a6, a7, b1, b3);
            }
        }
    }

    // ---- epilogue: reduce register accumulators into global gram ----
    const int g  = l >> 2;
    const int i2 = (l & 3) * 2;
#pragma unroll
    for (int mt = 0; mt < 2; mt++) {
#pragma unroll
        for (int nt = 0; nt < 8; nt++) {
            int row = mrow0 + 16 * mt + g;
            int col = ncol0 + 8 * nt + i2;
            atomicAdd(&d_igram[row * NDET + col],           acc[mt][nt][0]);
            atomicAdd(&d_igram[row * NDET + col + 1],       acc[mt][nt][1]);
            atomicAdd(&d_igram[(row + 8) * NDET + col],     acc[mt][nt][2]);
            atomicAdd(&d_igram[(row + 8) * NDET + col + 1], acc[mt][nt][3]);
        }
    }
}

// ---------------------------------------------------------------------------
// Kernel 2: everything O(N^2): conflict matrix, stable argsort-desc, greedy
// suppression, label filter, box-cover visibility, final scores.
// Single block, 128 threads.
// ---------------------------------------------------------------------------
__global__ void __launch_bounds__(128, 1)
finish_kernel(const float* __restrict__ boxes,
              const float* __restrict__ scores,
              const int*   __restrict__ labels,
              float*       __restrict__ out) {
    __shared__ float areas[NDET], ssc[NDET];
    __shared__ float x1s[NDET], y1s[NDET], x2s[NDET], y2s[NDET], bareas[NDET];
    __shared__ unsigned char confl[NDET * NDET];
    __shared__ int  ord[NDET];
    __shared__ unsigned char ks[NDET];     // keep, sorted order
    __shared__ unsigned char keepO[NDET];  // keep, original order

    const int j = threadIdx.x;

    areas[j] = (float)d_igram[j * NDET + j];
    ssc[j]   = scores[j];
    x1s[j] = boxes[j * 4 + 0];
    y1s[j] = boxes[j * 4 + 1];
    x2s[j] = boxes[j * 4 + 2];
    y2s[j] = boxes[j * 4 + 3];
    __syncthreads();

    // conflict[j][i] (symmetric)
    const float aj = areas[j];
    for (int i = 0; i < NDET; i++) {
        float inter = (float)d_igram[j * NDET + i];
        float ai    = areas[i];
        float amin  = fminf(ai, aj), amax = fmaxf(ai, aj);
        float iomin = inter / fmaxf(amin, 1.0f);
        float iomax = inter / fmaxf(amax, 1.0f);
        confl[j * NDET + i] = ((iomin > IOMIN_THRESH) || (iomax > IOMAX_THRESH)) ? 1 : 0;
    }

    // stable descending rank (matches stable argsort of -scores)
    const float sj = ssc[j];
    int r = 0;
    for (int i = 0; i < NDET; i++) {
        float si = ssc[i];
        r += (si > sj) || (si == sj && i < j);
    }
    ord[r] = j;
    ks[r]  = (aj > MIN_MASK_PIXELS) ? 1 : 0;
    __syncthreads();

    // greedy suppression in sorted order (serial over i, parallel over j)
    for (int i = 0; i < NDET; i++) {
        bool ki = ks[i];
        if (ki && j > i) {
            if (confl[ord[i] * NDET + ord[j]]) ks[j] = 0;
        }
        __syncthreads();
    }

    // unsort + label filter
    keepO[ord[j]] = ks[j];
    __syncthreads();
    unsigned char kj = (keepO[j] && (labels[j] == PED_LABEL)) ? 1 : 0;
    __syncthreads();
    keepO[j] = kj;
    {
        float wbx = x2s[j] - x1s[j], hbx = y2s[j] - y1s[j];
        bareas[j] = fmaxf(wbx * hbx, 1e-6f);
    }
    __syncthreads();

    // cover_j = max over occluders i != j of binter(i,j)/barea_j
    const bool high_j = (sj >= HIGH_SCORE_THRESH);
    float cover = 0.0f;
    const float bj = bareas[j];
    for (int i = 0; i < NDET; i++) {
        bool occ = (ssc[i] >= HIGH_SCORE_THRESH) && keepO[i] && (i != j);
        if (occ) {
            float ix1 = fmaxf(x1s[i], x1s[j]);
            float iy1 = fmaxf(y1s[i], y1s[j]);
            float ix2 = fminf(x2s[i], x2s[j]);
            float iy2 = fminf(y2s[i], y2s[j]);
            float bi  = fmaxf(ix2 - ix1, 0.0f) * fmaxf(iy2 - iy1, 0.0f);
            cover = fmaxf(cover, bi / bj);
        }
    }
    float vis = 1.0f - cover;
    bool finalk = keepO[j] && (high_j || (vis < VIS_THRESH));
    out[j] = sj * (finalk ? 1.0f : 0.0f);
}

// ---------------------------------------------------------------------------
// kernel_launch — inputs (metadata order): boxes f32[128,4], scores f32[128],
// labels i32[128], masks f32[128,1,608,1088]; output f32[128].
// ---------------------------------------------------------------------------
extern "C" void kernel_launch(void* const* d_in, const int* in_sizes, int n_in,
                              void* d_out, int out_size) {
    const float* boxes  = (const float*)d_in[0];
    const float* scores = (const float*)d_in[1];
    const int*   labels = (const int*)d_in[2];
    const float* masks  = (const float*)d_in[3];
    float* out = (float*)d_out;

    zero_gram_kernel<<<GRAMN / 256, 256>>>();
    gram_kernel<<<GRID, 256>>>(masks);
    finish_kernel<<<1, 128>>>(boxes, scores, labels, out);
}

// round 4
// speedup vs baseline: 1.0568x; 1.0568x over previous
#include <cuda_runtime.h>
#include <cstdint>

// ---------------------------------------------------------------------------
// Problem constants
// ---------------------------------------------------------------------------
#define NDET   128
#define HWPIX  661504            // 608 * 1088
#define HW4    (HWPIX / 4)       // float4 per mask row
#define NCHUNK (HWPIX / 128)     // 5168 K-chunks of 128 pixels
#define GRAMN  (NDET * NDET)
#define GRID   148

#define MASK_SCORE_THRESH 0.5f
#define MIN_MASK_PIXELS   20.0f
#define IOMIN_THRESH      0.9f
#define IOMAX_THRESH      0.5f
#define HIGH_SCORE_THRESH 0.5f
#define VIS_THRESH        0.1f
#define PED_LABEL         1

// Row stride of the s8 smem tile in bytes (128 data + 16 pad -> conflict-free
// ldmatrix: 8 consecutive rows land in distinct 16B bank groups).
#define TPITCH 144

// Global scratch: 128x128 s32 Gram. Only upper triangle (col >= row) is valid.
__device__ int d_igram[GRAMN];

// ---------------------------------------------------------------------------
// PTX helpers (portable sm_80+ tensor path; PTX target is plain sm_100)
// ---------------------------------------------------------------------------
__device__ __forceinline__ uint32_t smem_u32(const void* p) {
    uint32_t a;
    asm("{ .reg .u64 t; cvta.to.shared.u64 t, %1; cvt.u32.u64 %0, t; }"
        : "=r"(a) : "l"(p));
    return a;
}

#define LDSM_X4(r0, r1, r2, r3, addr)                                      \
    asm volatile("ldmatrix.sync.aligned.m8n8.x4.shared.b16 "               \
                 "{%0,%1,%2,%3}, [%4];"                                    \
                 : "=r"(r0), "=r"(r1), "=r"(r2), "=r"(r3) : "r"(addr))

#define IMMA16832(c, a0, a1, a2, a3, b0, b1)                               \
    asm volatile("mma.sync.aligned.m16n8k32.row.col.s32.s8.s8.s32 "        \
                 "{%0,%1,%2,%3}, {%4,%5,%6,%7}, {%8,%9}, {%0,%1,%2,%3};"   \
                 : "+r"((c)[0]), "+r"((c)[1]), "+r"((c)[2]), "+r"((c)[3])  \
                 : "r"(a0), "r"(a1), "r"(a2), "r"(a3), "r"(b0), "r"(b1))

// ---------------------------------------------------------------------------
// Kernel 0: zero the gram accumulator
// ---------------------------------------------------------------------------
__global__ void zero_gram_kernel() {
    int i = blockIdx.x * blockDim.x + threadIdx.x;
    if (i < GRAMN) d_igram[i] = 0;
}

// ---------------------------------------------------------------------------
// Kernel 1: fused binarize + upper-triangular Gram.
// 148 persistent CTAs x 512 threads (16 warps, 4/SMSP).
// Per 128-pixel chunk:
//   - each warp loads 8 rows x 128 px fp32 (prefetched one chunk ahead; raw
//     float4 kept live so the load-wait lands after a full MMA phase),
//   - binarize -> packed s8 {0,1} -> 128x144B smem tile (double-buffered,
//     ONE __syncthreads per chunk),
//   - MMA: upper triangle only. 32x32 warp tiles. Warps 0-3: diagonal tiles,
//     full K, below-diagonal micro-tiles skipped. Warps 4-15: the 6
//     off-diagonal tiles, two warps each splitting K in half. Balanced to
//     <= 72 IMMAs per SMSP per chunk.
// Epilogue: atomic reduce into d_igram (upper triangle only).
// ---------------------------------------------------------------------------
__global__ void __launch_bounds__(512, 1)
gram_kernel(const float* __restrict__ masks) {
    __shared__ __align__(16) unsigned char tile[2][NDET * TPITCH];

    const int tid = threadIdx.x;
    const int w   = tid >> 5;
    const int l   = tid & 31;

    // ldmatrix lane addressing
    const uint32_t lrow  = (uint32_t)(l & 15);
    const uint32_t lhalf = (uint32_t)((l >> 4) * 16);

    // ---- warp -> (tile row, tile col, k-range) schedule ----
    int trow, tcol, s_lo, s_hi;
    bool diag;
    if (w < 4) {                     // diagonal tiles, full K
        trow = w; tcol = w; s_lo = 0; s_hi = 4; diag = true;
    } else {                         // off-diagonal tiles, K split in half
        static const int OR[6] = {0, 0, 0, 1, 1, 2};
        static const int OC[6] = {1, 2, 3, 2, 3, 3};
        int p = (w - 4) >> 1;
        trow = OR[p]; tcol = OC[p];
        s_lo = (w & 1) ? 2 : 0; s_hi = s_lo + 2; diag = false;
    }

    int acc[2][4][4];
#pragma unroll
    for (int mi = 0; mi < 2; mi++)
#pragma unroll
        for (int g = 0; g < 4; g++)
#pragma unroll
            for (int e = 0; e < 4; e++) acc[mi][g][e] = 0;

    // load assignment: warp w loads rows 8w..8w+7, lane l -> float4 #l
    const float4* m4 = (const float4*)masks;
    const size_t  row_base = (size_t)(8 * w) * HW4 + l;

    float4 v[8];

    // prefetch chunk 0 (raw fp32; binarized at consumption)
    int k = blockIdx.x;
    if (k < NCHUNK) {
        const float4* p = m4 + row_base + (size_t)k * 32;
#pragma unroll
        for (int r = 0; r < 8; r++) v[r] = p[(size_t)r * HW4];
    }

    int b = 0;
    for (; k < NCHUNK; k += GRID, b ^= 1) {
        // ---- binarize + store tile (waits on this chunk's loads) ----
        unsigned char* tb = tile[b];
#pragma unroll
        for (int r = 0; r < 8; r++) {
            uint32_t pk = (v[r].x > MASK_SCORE_THRESH ? 0x01u       : 0u)
                        | (v[r].y > MASK_SCORE_THRESH ? 0x0100u     : 0u)
                        | (v[r].z > MASK_SCORE_THRESH ? 0x010000u   : 0u)
                        | (v[r].w > MASK_SCORE_THRESH ? 0x01000000u : 0u);
            uint32_t off = (uint32_t)(8 * w + r) * TPITCH + (uint32_t)(4 * l);
            *(uint32_t*)(tb + off) = pk;
        }

        __syncthreads();   // tile[b] ready; also protects tile[b^1] reuse

        // ---- issue prefetch for next chunk (covered by MMA below) ----
        int kn = k + GRID;
        if (kn < NCHUNK) {
            const float4* p = m4 + row_base + (size_t)kn * 32;
#pragma unroll
            for (int r = 0; r < 8; r++) v[r] = p[(size_t)r * HW4];
        }

        // ---- MMA phase on tile[b] ----
        const uint32_t tbase = smem_u32(tb);
        const uint32_t abase = tbase + (uint32_t)(trow * 32) * TPITCH + lrow * TPITCH;
        const uint32_t bbase = tbase + (uint32_t)(tcol * 32) * TPITCH + lrow * TPITCH;

        for (int s = s_lo; s < s_hi; s++) {
            const uint32_t kb = (uint32_t)(32 * s) + lhalf;

            uint32_t a0, a1, a2, a3, a4, a5, a6, a7;
            LDSM_X4(a0, a1, a2, a3, abase + kb);
            LDSM_X4(a4, a5, a6, a7, abase + 16u * TPITCH + kb);
            uint32_t b0, b1, b2, b3, b4, b5, b6, b7;
            LDSM_X4(b0, b1, b2, b3, bbase + kb);
            LDSM_X4(b4, b5, b6, b7, bbase + 16u * TPITCH + kb);

            IMMA16832(acc[0][0], a0, a1, a2, a3, b0, b2);
            IMMA16832(acc[0][1], a0, a1, a2, a3, b1, b3);
            IMMA16832(acc[0][2], a0, a1, a2, a3, b4, b6);
            IMMA16832(acc[0][3], a0, a1, a2, a3, b5, b7);
            if (!diag) {   // rows 16-31 x cols 0-15 are below the diagonal on diag tiles
                IMMA16832(acc[1][0], a4, a5, a6, a7, b0, b2);
                IMMA16832(acc[1][1], a4, a5, a6, a7, b1, b3);
            }
            IMMA16832(acc[1][2], a4, a5, a6, a7, b4, b6);
            IMMA16832(acc[1][3], a4, a5, a6, a7, b5, b7);
        }
    }

    // ---- epilogue: reduce register accumulators into global gram ----
    const int g4 = l >> 2;
    const int i2 = (l & 3) * 2;
#pragma unroll
    for (int mi = 0; mi < 2; mi++) {
#pragma unroll
        for (int g = 0; g < 4; g++) {
            if (diag && mi == 1 && g < 2) continue;   // never computed
            int row = trow * 32 + 16 * mi + g4;
            int col = tcol * 32 + 8 * g + i2;
            atomicAdd(&d_igram[row * NDET + col],           acc[mi][g][0]);
            atomicAdd(&d_igram[row * NDET + col + 1],       acc[mi][g][1]);
            atomicAdd(&d_igram[(row + 8) * NDET + col],     acc[mi][g][2]);
            atomicAdd(&d_igram[(row + 8) * NDET + col + 1], acc[mi][g][3]);
        }
    }
}

// ---------------------------------------------------------------------------
// Kernel 2: O(N^2) finish. Gram is upper-triangular: read [min][max].
// ---------------------------------------------------------------------------
__global__ void __launch_bounds__(128, 1)
finish_kernel(const float* __restrict__ boxes,
              const float* __restrict__ scores,
              const int*   __restrict__ labels,
              float*       __restrict__ out) {
    __shared__ float areas[NDET], ssc[NDET];
    __shared__ float x1s[NDET], y1s[NDET], x2s[NDET], y2s[NDET], bareas[NDET];
    __shared__ unsigned char confl[NDET * NDET];
    __shared__ int  ord[NDET];
    __shared__ unsigned char ks[NDET];     // keep, sorted order
    __shared__ unsigned char keepO[NDET];  // keep, original order

    const int j = threadIdx.x;

    areas[j] = (float)d_igram[j * NDET + j];
    ssc[j]   = scores[j];
    x1s[j] = boxes[j * 4 + 0];
    y1s[j] = boxes[j * 4 + 1];
    x2s[j] = boxes[j * 4 + 2];
    y2s[j] = boxes[j * 4 + 3];
    __syncthreads();

    // conflict[j][i] (symmetric; gram stored upper-triangular)
    const float aj = areas[j];
    for (int i = 0; i < NDET; i++) {
        int lo = (i < j) ? i : j;
        int hi = (i < j) ? j : i;
        float inter = (float)d_igram[lo * NDET + hi];
        float ai    = areas[i];
        float amin  = fminf(ai, aj), amax = fmaxf(ai, aj);
        float iomin = inter / fmaxf(amin, 1.0f);
        float iomax = inter / fmaxf(amax, 1.0f);
        confl[j * NDET + i] = ((iomin > IOMIN_THRESH) || (iomax > IOMAX_THRESH)) ? 1 : 0;
    }

    // stable descending rank (matches stable argsort of -scores)
    const float sj = ssc[j];
    int r = 0;
    for (int i = 0; i < NDET; i++) {
        float si = ssc[i];
        r += (si > sj) || (si == sj && i < j);
    }
    ord[r] = j;
    ks[r]  = (aj > MIN_MASK_PIXELS) ? 1 : 0;
    __syncthreads();

    // greedy suppression in sorted order (serial over i, parallel over j)
    for (int i = 0; i < NDET; i++) {
        bool ki = ks[i];
        if (ki && j > i) {
            if (confl[ord[i] * NDET + ord[j]]) ks[j] = 0;
        }
        __syncthreads();
    }

    // unsort + label filter
    keepO[ord[j]] = ks[j];
    __syncthreads();
    unsigned char kj = (keepO[j] && (labels[j] == PED_LABEL)) ? 1 : 0;
    __syncthreads();
    keepO[j] = kj;
    {
        float wbx = x2s[j] - x1s[j], hbx = y2s[j] - y1s[j];
        bareas[j] = fmaxf(wbx * hbx, 1e-6f);
    }
    __syncthreads();

    // cover_j = max over occluders i != j of binter(i,j)/barea_j
    const bool high_j = (sj >= HIGH_SCORE_THRESH);
    float cover = 0.0f;
    const float bj = bareas[j];
    for (int i = 0; i < NDET; i++) {
        bool occ = (ssc[i] >= HIGH_SCORE_THRESH) && keepO[i] && (i != j);
        if (occ) {
            float ix1 = fmaxf(x1s[i], x1s[j]);
            float iy1 = fmaxf(y1s[i], y1s[j]);
            float ix2 = fminf(x2s[i], x2s[j]);
            float iy2 = fminf(y2s[i], y2s[j]);
            float bi  = fmaxf(ix2 - ix1, 0.0f) * fmaxf(iy2 - iy1, 0.0f);
            cover = fmaxf(cover, bi / bj);
        }
    }
    float vis = 1.0f - cover;
    bool finalk = keepO[j] && (high_j || (vis < VIS_THRESH));
    out[j] = sj * (finalk ? 1.0f : 0.0f);
}

// ---------------------------------------------------------------------------
// kernel_launch — inputs (metadata order): boxes f32[128,4], scores f32[128],
// labels i32[128], masks f32[128,1,608,1088]; output f32[128].
// ---------------------------------------------------------------------------
extern "C" void kernel_launch(void* const* d_in, const int* in_sizes, int n_in,
                              void* d_out, int out_size) {
    const float* boxes  = (const float*)d_in[0];
    const float* scores = (const float*)d_in[1];
    const int*   labels = (const int*)d_in[2];
    const float* masks  = (const float*)d_in[3];
    float* out = (float*)d_out;

    zero_gram_kernel<<<GRAMN / 256, 256>>>();
    gram_kernel<<<GRID, 512>>>(masks);
    finish_kernel<<<1, 128>>>(boxes, scores, labels, out);
}

// round 5
// speedup vs baseline: 1.0905x; 1.0320x over previous
#include <cuda_runtime.h>
#include <cstdint>

// ---------------------------------------------------------------------------
// Problem constants
// ---------------------------------------------------------------------------
#define NDET   128
#define HWPIX  661504            // 608 * 1088
#define NCHUNK (HWPIX / 128)     // 5168 K-chunks of 128 pixels
#define GRAMN  (NDET * NDET)
#define GRID   148

#define MASK_SCORE_THRESH 0.5f
#define MIN_MASK_PIXELS   20.0f
#define IOMIN_THRESH      0.9f
#define IOMAX_THRESH      0.5f
#define HIGH_SCORE_THRESH 0.5f
#define VIS_THRESH        0.1f
#define PED_LABEL         1

// s8 tile row pitch (128 data + 16 pad -> conflict-free ldmatrix)
#define TPITCH 144
#define TILE_BYTES (NDET * TPITCH)      // 18432

// fp32 stage: 128 rows x 512 B
#define STAGE_BYTES (NDET * 512)        // 65536
#define NSTAGE 3
#define SMEM_TOTAL (NSTAGE * STAGE_BYTES + TILE_BYTES)   // 215040

// Global scratch: 128x128 s32 Gram. Only upper triangle (col >= row) valid.
__device__ int d_igram[GRAMN];

// ---------------------------------------------------------------------------
// PTX helpers (sm_80+ portable; PTX target is plain sm_100)
// ---------------------------------------------------------------------------
__device__ __forceinline__ uint32_t smem_u32(const void* p) {
    uint32_t a;
    asm("{ .reg .u64 t; cvta.to.shared.u64 t, %1; cvt.u32.u64 %0, t; }"
        : "=r"(a) : "l"(p));
    return a;
}

#define CP_ASYNC16(dst, src)                                               \
    asm volatile("cp.async.cg.shared.global [%0], [%1], 16;"               \
                 :: "r"(dst), "l"(src) : "memory")
#define CP_COMMIT() asm volatile("cp.async.commit_group;" ::: "memory")
#define CP_WAIT2()  asm volatile("cp.async.wait_group 2;" ::: "memory")

#define LDSM_X4(r0, r1, r2, r3, addr)                                      \
    asm volatile("ldmatrix.sync.aligned.m8n8.x4.shared.b16 "               \
                 "{%0,%1,%2,%3}, [%4];"                                    \
                 : "=r"(r0), "=r"(r1), "=r"(r2), "=r"(r3) : "r"(addr))

#define IMMA16832(c, a0, a1, a2, a3, b0, b1)                               \
    asm volatile("mma.sync.aligned.m16n8k32.row.col.s32.s8.s8.s32 "        \
                 "{%0,%1,%2,%3}, {%4,%5,%6,%7}, {%8,%9}, {%0,%1,%2,%3};"   \
                 : "+r"((c)[0]), "+r"((c)[1]), "+r"((c)[2]), "+r"((c)[3])  \
                 : "r"(a0), "r"(a1), "r"(a2), "r"(a3), "r"(b0), "r"(b1))

// ---------------------------------------------------------------------------
// Kernel 0: zero the gram accumulator
// ---------------------------------------------------------------------------
__global__ void zero_gram_kernel() {
    int i = blockIdx.x * blockDim.x + threadIdx.x;
    if (i < GRAMN) d_igram[i] = 0;
}

// ---------------------------------------------------------------------------
// Kernel 1: fused binarize + upper-triangular Gram, cp.async 3-stage pipeline.
// 148 persistent CTAs x 512 threads (16 warps).
// Per chunk: wait oldest stage -> sync -> binarize fp32 stage -> s8 tile ->
// sync -> issue cp.async for chunk k+3*GRID into freed stage -> MMA on tile.
// Warp w copies/binarizes rows 8w..8w+7; lane l owns bytes 16l..16l+15 of
// each row (its own cp.async data -> per-thread wait_group suffices).
// MMA: 32x32 warp tiles, upper triangle, K split over warp pairs (<=40
// IMMA/warp/chunk). Epilogue: atomic reduce into d_igram.
// ---------------------------------------------------------------------------
__global__ void __launch_bounds__(512, 1)
gram_kernel(const float* __restrict__ masks) {
    extern __shared__ __align__(16) char smem[];
    char* tilec = smem + NSTAGE * STAGE_BYTES;

    const int tid = threadIdx.x;
    const int w   = tid >> 5;
    const int l   = tid & 31;

    const uint32_t lrow  = (uint32_t)(l & 15);
    const uint32_t lhalf = (uint32_t)((l >> 4) * 16);

    // ---- warp -> (tile row, tile col, k-range) schedule ----
    int trow, tcol, s_lo, s_hi;
    bool diag;
    if (w < 4) {
        trow = w; tcol = w; s_lo = 0; s_hi = 4; diag = true;
    } else {
        static const int OR[6] = {0, 0, 0, 1, 1, 2};
        static const int OC[6] = {1, 2, 3, 2, 3, 3};
        int p = (w - 4) >> 1;
        trow = OR[p]; tcol = OC[p];
        s_lo = (w & 1) ? 2 : 0; s_hi = s_lo + 2; diag = false;
    }

    int acc[2][4][4];
#pragma unroll
    for (int mi = 0; mi < 2; mi++)
#pragma unroll
        for (int g = 0; g < 4; g++)
#pragma unroll
            for (int e = 0; e < 4; e++) acc[mi][g][e] = 0;

    // per-thread copy addressing: rows 8w..8w+7, lane l -> bytes 16l..16l+15
    const char* gbase = (const char*)masks +
                        ((size_t)(8 * w) * HWPIX) * 4 + (size_t)(16 * l);
    const uint32_t srow = (uint32_t)(8 * w) * 512u + (uint32_t)(16 * l);
    const uint32_t smem_base = smem_u32(smem);

    const uint32_t tbase = smem_u32(tilec);
    const uint32_t abase = tbase + (uint32_t)(trow * 32 + (int)lrow) * TPITCH;
    const uint32_t bbase = tbase + (uint32_t)(tcol * 32 + (int)lrow) * TPITCH;

    // ---- prologue: fill the 3-stage pipeline (always commit 3 groups) ----
    const int k0 = blockIdx.x;
#pragma unroll
    for (int s = 0; s < NSTAGE; s++) {
        int kk = k0 + s * GRID;
        if (kk < NCHUNK) {
            const char* g = gbase + (size_t)kk * 512;
            uint32_t d = smem_base + (uint32_t)s * STAGE_BYTES + srow;
#pragma unroll
            for (int r = 0; r < 8; r++)
                CP_ASYNC16(d + (uint32_t)r * 512u, g + (size_t)r * HWPIX * 4);
        }
        CP_COMMIT();
    }

    int sk = 0;
    for (int k = k0; k < NCHUNK; k += GRID) {
        CP_WAIT2();          // oldest group (this stage) complete
        __syncthreads();     // MMA(prev) done reading tile

        // ---- binarize stage[sk] -> s8 tile ----
        const float4* st = (const float4*)(smem + sk * STAGE_BYTES);
#pragma unroll
        for (int r = 0; r < 8; r++) {
            float4 v = st[(8 * w + r) * 32 + l];
            uint32_t pk = (v.x > MASK_SCORE_THRESH ? 0x01u       : 0u)
                        | (v.y > MASK_SCORE_THRESH ? 0x0100u     : 0u)
                        | (v.z > MASK_SCORE_THRESH ? 0x010000u   : 0u)
                        | (v.w > MASK_SCORE_THRESH ? 0x01000000u : 0u);
            *(uint32_t*)(tilec + (uint32_t)(8 * w + r) * TPITCH + 4u * l) = pk;
        }
        __syncthreads();     // tile ready; stage[sk] fully consumed

        // ---- refill stage[sk] with chunk k+3*GRID (always commit) ----
        {
            int kn = k + NSTAGE * GRID;
            if (kn < NCHUNK) {
                const char* g = gbase + (size_t)kn * 512;
                uint32_t d = smem_base + (uint32_t)sk * STAGE_BYTES + srow;
#pragma unroll
                for (int r = 0; r < 8; r++)
                    CP_ASYNC16(d + (uint32_t)r * 512u, g + (size_t)r * HWPIX * 4);
            }
            CP_COMMIT();
        }

        // ---- MMA phase on tile ----
        for (int s = s_lo; s < s_hi; s++) {
            const uint32_t kb = (uint32_t)(32 * s) + lhalf;

            uint32_t a0, a1, a2, a3, a4, a5, a6, a7;
            LDSM_X4(a0, a1, a2, a3, abase + kb);
            LDSM_X4(a4, a5, a6, a7, abase + 16u * TPITCH + kb);
            uint32_t b0, b1, b2, b3, b4, b5, b6, b7;
            LDSM_X4(b0, b1, b2, b3, bbase + kb);
            LDSM_X4(b4, b5, b6, b7, bbase + 16u * TPITCH + kb);

            IMMA16832(acc[0][0], a0, a1, a2, a3, b0, b2);
            IMMA16832(acc[0][1], a0, a1, a2, a3, b1, b3);
            IMMA16832(acc[0][2], a0, a1, a2, a3, b4, b6);
            IMMA16832(acc[0][3], a0, a1, a2, a3, b5, b7);
            if (!diag) {
                IMMA16832(acc[1][0], a4, a5, a6, a7, b0, b2);
                IMMA16832(acc[1][1], a4, a5, a6, a7, b1, b3);
            }
            IMMA16832(acc[1][2], a4, a5, a6, a7, b4, b6);
            IMMA16832(acc[1][3], a4, a5, a6, a7, b5, b7);
        }

        sk = (sk + 1) % NSTAGE;
    }

    // ---- epilogue: reduce register accumulators into global gram ----
    const int g4 = l >> 2;
    const int i2 = (l & 3) * 2;
#pragma unroll
    for (int mi = 0; mi < 2; mi++) {
#pragma unroll
        for (int g = 0; g < 4; g++) {
            if (diag && mi == 1 && g < 2) continue;   // never computed
            int row = trow * 32 + 16 * mi + g4;
            int col = tcol * 32 + 8 * g + i2;
            atomicAdd(&d_igram[row * NDET + col],           acc[mi][g][0]);
            atomicAdd(&d_igram[row * NDET + col + 1],       acc[mi][g][1]);
            atomicAdd(&d_igram[(row + 8) * NDET + col],     acc[mi][g][2]);
            atomicAdd(&d_igram[(row + 8) * NDET + col + 1], acc[mi][g][3]);
        }
    }
}

// ---------------------------------------------------------------------------
// Kernel 2: O(N^2) finish. Gram is upper-triangular: read [min][max].
// ---------------------------------------------------------------------------
__global__ void __launch_bounds__(128, 1)
finish_kernel(const float* __restrict__ boxes,
              const float* __restrict__ scores,
              const int*   __restrict__ labels,
              float*       __restrict__ out) {
    __shared__ float areas[NDET], ssc[NDET];
    __shared__ float x1s[NDET], y1s[NDET], x2s[NDET], y2s[NDET], bareas[NDET];
    __shared__ unsigned char confl[NDET * NDET];
    __shared__ int  ord[NDET];
    __shared__ unsigned char ks[NDET];
    __shared__ unsigned char keepO[NDET];

    const int j = threadIdx.x;

    areas[j] = (float)d_igram[j * NDET + j];
    ssc[j]   = scores[j];
    x1s[j] = boxes[j * 4 + 0];
    y1s[j] = boxes[j * 4 + 1];
    x2s[j] = boxes[j * 4 + 2];
    y2s[j] = boxes[j * 4 + 3];
    __syncthreads();

    const float aj = areas[j];
    for (int i = 0; i < NDET; i++) {
        int lo = (i < j) ? i : j;
        int hi = (i < j) ? j : i;
        float inter = (float)d_igram[lo * NDET + hi];
        float ai    = areas[i];
        float amin  = fminf(ai, aj), amax = fmaxf(ai, aj);
        float iomin = inter / fmaxf(amin, 1.0f);
        float iomax = inter / fmaxf(amax, 1.0f);
        confl[j * NDET + i] = ((iomin > IOMIN_THRESH) || (iomax > IOMAX_THRESH)) ? 1 : 0;
    }

    // stable descending rank
    const float sj = ssc[j];
    int r = 0;
    for (int i = 0; i < NDET; i++) {
        float si = ssc[i];
        r += (si > sj) || (si == sj && i < j);
    }
    ord[r] = j;
    ks[r]  = (aj > MIN_MASK_PIXELS) ? 1 : 0;
    __syncthreads();

    // greedy suppression
    for (int i = 0; i < NDET; i++) {
        bool ki = ks[i];
        if (ki && j > i) {
            if (confl[ord[i] * NDET + ord[j]]) ks[j] = 0;
        }
        __syncthreads();
    }

    // unsort + label filter
    keepO[ord[j]] = ks[j];
    __syncthreads();
    unsigned char kj = (keepO[j] && (labels[j] == PED_LABEL)) ? 1 : 0;
    __syncthreads();
    keepO[j] = kj;
    {
        float wbx = x2s[j] - x1s[j], hbx = y2s[j] - y1s[j];
        bareas[j] = fmaxf(wbx * hbx, 1e-6f);
    }
    __syncthreads();

    // visibility
    const bool high_j = (sj >= HIGH_SCORE_THRESH);
    float cover = 0.0f;
    const float bj = bareas[j];
    for (int i = 0; i < NDET; i++) {
        bool occ = (ssc[i] >= HIGH_SCORE_THRESH) && keepO[i] && (i != j);
        if (occ) {
            float ix1 = fmaxf(x1s[i], x1s[j]);
            float iy1 = fmaxf(y1s[i], y1s[j]);
            float ix2 = fminf(x2s[i], x2s[j]);
            float iy2 = fminf(y2s[i], y2s[j]);
            float bi  = fmaxf(ix2 - ix1, 0.0f) * fmaxf(iy2 - iy1, 0.0f);
            cover = fmaxf(cover, bi / bj);
        }
    }
    float vis = 1.0f - cover;
    bool finalk = keepO[j] && (high_j || (vis < VIS_THRESH));
    out[j] = sj * (finalk ? 1.0f : 0.0f);
}

// ---------------------------------------------------------------------------
// kernel_launch
// ---------------------------------------------------------------------------
extern "C" void kernel_launch(void* const* d_in, const int* in_sizes, int n_in,
                              void* d_out, int out_size) {
    const float* boxes  = (const float*)d_in[0];
    const float* scores = (const float*)d_in[1];
    const int*   labels = (const int*)d_in[2];
    const float* masks  = (const float*)d_in[3];
    float* out = (float*)d_out;

    static bool attr_set = false;
    if (!attr_set) {
        cudaFuncSetAttribute(gram_kernel,
                             cudaFuncAttributeMaxDynamicSharedMemorySize,
                             SMEM_TOTAL);
        attr_set = true;
    }

    zero_gram_kernel<<<GRAMN / 256, 256>>>();
    gram_kernel<<<GRID, 512, SMEM_TOTAL>>>(masks);
    finish_kernel<<<1, 128>>>(boxes, scores, labels, out);
}

// round 7
// speedup vs baseline: 1.0935x; 1.0027x over previous
#include <cuda_runtime.h>
#include <cstdint>

// ---------------------------------------------------------------------------
// Problem constants
// ---------------------------------------------------------------------------
#define NDET   128
#define HWPIX  661504            // 608 * 1088
#define NCHUNK (HWPIX / 128)     // 5168 K-chunks of 128 pixels
#define GRAMN  (NDET * NDET)
#define GRID   148

#define MASK_SCORE_THRESH 0.5f
#define MIN_MASK_PIXELS   20.0f
#define IOMIN_THRESH      0.9f
#define IOMAX_THRESH      0.5f
#define HIGH_SCORE_THRESH 0.5f
#define VIS_THRESH        0.1f
#define PED_LABEL         1

// s8 tile row pitch (128 data + 16 pad -> conflict-free ldmatrix)
#define TPITCH 144
#define TILE_BYTES (NDET * TPITCH)      // 18432

// fp32 stage: 128 rows x 512 B, double buffered (matches the 2 s8 tiles)
#define STAGE_BYTES (NDET * 512)        // 65536
#define NSTAGE 2
#define SMEM_TOTAL (NSTAGE * STAGE_BYTES + 2 * TILE_BYTES)   // 167936

// Named barrier ids: FULL[b] = 1+b, FREE[b] = 3+b
#define BAR_FULL(b) (1 + (b))
#define BAR_FREE(b) (3 + (b))

// Global scratch: 128x128 s32 Gram. Upper triangle (col >= row) valid.
// Zero-initialized at module load; re-zeroed by zero_gram_kernel at the END
// of every kernel_launch invocation (so each replay starts from zeros).
__device__ int d_igram[GRAMN];

// ---------------------------------------------------------------------------
// PTX helpers (sm_80+ portable; PTX target is plain sm_100)
// ---------------------------------------------------------------------------
__device__ __forceinline__ uint32_t smem_u32(const void* p) {
    uint32_t a;
    asm("{ .reg .u64 t; cvta.to.shared.u64 t, %1; cvt.u32.u64 %0, t; }"
        : "=r"(a) : "l"(p));
    return a;
}

#define CP_ASYNC16(dst, src)                                               \
    asm volatile("cp.async.cg.shared.global [%0], [%1], 16;"               \
                 :: "r"(dst), "l"(src) : "memory")
#define CP_COMMIT() asm volatile("cp.async.commit_group;" ::: "memory")
#define CP_WAIT1()  asm volatile("cp.async.wait_group 1;" ::: "memory")

#define BAR_SYNC(id)   asm volatile("bar.sync %0, 512;"   :: "r"(id) : "memory")
#define BAR_ARRIVE(id) asm volatile("bar.arrive %0, 512;" :: "r"(id) : "memory")
#define MEMBAR_CTA()   asm volatile("membar.cta;" ::: "memory")

#define LDSM_X4(r0, r1, r2, r3, addr)                                      \
    asm volatile("ldmatrix.sync.aligned.m8n8.x4.shared.b16 "               \
                 "{%0,%1,%2,%3}, [%4];"                                    \
                 : "=r"(r0), "=r"(r1), "=r"(r2), "=r"(r3) : "r"(addr))

#define IMMA16832(c, a0, a1, a2, a3, b0, b1)                               \
    asm volatile("mma.sync.aligned.m16n8k32.row.col.s32.s8.s8.s32 "        \
                 "{%0,%1,%2,%3}, {%4,%5,%6,%7}, {%8,%9}, {%0,%1,%2,%3};"   \
                 : "+r"((c)[0]), "+r"((c)[1]), "+r"((c)[2]), "+r"((c)[3])  \
                 : "r"(a0), "r"(a1), "r"(a2), "r"(a3), "r"(b0), "r"(b1))

// (v > 0.5f) ? 0xFFFFFFFF : 0
__device__ __forceinline__ uint32_t setgt(float v) {
    uint32_t s;
    asm("set.gt.u32.f32 %0, %1, %2;" : "=r"(s) : "f"(v), "f"(MASK_SCORE_THRESH));
    return s;
}

// ---------------------------------------------------------------------------
// MMA job helper: one 32x32 tile (trow,tcol), ksteps [s_lo, s_hi).
// diag=true skips the 2 below-diagonal micro-tiles.
// ---------------------------------------------------------------------------
__device__ __forceinline__ void mma_job(int acc[2][4][4], uint32_t tbase,
                                        int trow, int tcol, int s_lo, int s_hi,
                                        bool diag, uint32_t lrow, uint32_t lhalf) {
    const uint32_t abase = tbase + (uint32_t)(trow * 32 + (int)lrow) * TPITCH;
    const uint32_t bbase = tbase + (uint32_t)(tcol * 32 + (int)lrow) * TPITCH;
    for (int s = s_lo; s < s_hi; s++) {
        const uint32_t kb = (uint32_t)(32 * s) + lhalf;
        uint32_t a0, a1, a2, a3, a4, a5, a6, a7;
        LDSM_X4(a0, a1, a2, a3, abase + kb);
        LDSM_X4(a4, a5, a6, a7, abase + 16u * TPITCH + kb);
        uint32_t b0, b1, b2, b3, b4, b5, b6, b7;
        LDSM_X4(b0, b1, b2, b3, bbase + kb);
        LDSM_X4(b4, b5, b6, b7, bbase + 16u * TPITCH + kb);

        IMMA16832(acc[0][0], a0, a1, a2, a3, b0, b2);
        IMMA16832(acc[0][1], a0, a1, a2, a3, b1, b3);
        IMMA16832(acc[0][2], a0, a1, a2, a3, b4, b6);
        IMMA16832(acc[0][3], a0, a1, a2, a3, b5, b7);
        if (!diag) {
            IMMA16832(acc[1][0], a4, a5, a6, a7, b0, b2);
            IMMA16832(acc[1][1], a4, a5, a6, a7, b1, b3);
        }
        IMMA16832(acc[1][2], a4, a5, a6, a7, b4, b6);
        IMMA16832(acc[1][3], a4, a5, a6, a7, b5, b7);
    }
}

__device__ __forceinline__ void store_job(int acc[2][4][4], int trow, int tcol,
                                          bool diag, int l) {
    const int g4 = l >> 2;
    const int i2 = (l & 3) * 2;
#pragma unroll
    for (int mi = 0; mi < 2; mi++) {
#pragma unroll
        for (int g = 0; g < 4; g++) {
            if (diag && mi == 1 && g < 2) continue;
            int row = trow * 32 + 16 * mi + g4;
            int col = tcol * 32 + 8 * g + i2;
            atomicAdd(&d_igram[row * NDET + col],           acc[mi][g][0]);
            atomicAdd(&d_igram[row * NDET + col + 1],       acc[mi][g][1]);
            atomicAdd(&d_igram[(row + 8) * NDET + col],     acc[mi][g][2]);
            atomicAdd(&d_igram[(row + 8) * NDET + col + 1], acc[mi][g][3]);
        }
    }
}

// ---------------------------------------------------------------------------
// Kernel: fused binarize + upper-triangular Gram, warp-specialized.
// 148 persistent CTAs x 512 threads.
//   warps 0-7  (producers): cp.async fp32 stage (2-deep) -> binarize ->
//                           s8 tile[b] (double buffered)
//   warps 8-15 (consumers): ldmatrix + IMMA on tile[b]
// Handshake: named barriers FULL[b] / FREE[b], count 512 (producers arrive
// FULL & sync FREE; consumers sync FULL & arrive FREE). No __syncthreads in
// the main loop -> producer DRAM streaming overlaps consumer tensor work.
// ---------------------------------------------------------------------------
__global__ void __launch_bounds__(512, 1)
gram_kernel(const float* __restrict__ masks) {
    extern __shared__ __align__(16) char smem[];
    char* tiles = smem + NSTAGE * STAGE_BYTES;   // 2 tiles of TILE_BYTES

    const int tid = threadIdx.x;
    const int w   = tid >> 5;
    const int l   = tid & 31;
    const int k0  = blockIdx.x;

    if (w < 8) {
        // ================= PRODUCER =================
        const int p = w;                       // rows 16p..16p+15
        const char* gbase = (const char*)masks +
                            (size_t)(16 * p) * HWPIX * 4 + (size_t)(16 * l);
        const uint32_t smem_base = smem_u32(smem);
        const uint32_t srow = (uint32_t)(16 * p) * 512u + (uint32_t)(16 * l);

        // prologue: fill both stages
#pragma unroll
        for (int s = 0; s < NSTAGE; s++) {
            int kk = k0 + s * GRID;
            if (kk < NCHUNK) {
                const char* g = gbase + (size_t)kk * 512;
                uint32_t d = smem_base + (uint32_t)s * STAGE_BYTES + srow;
#pragma unroll
                for (int r = 0; r < 16; r++)
                    CP_ASYNC16(d + (uint32_t)r * 512u, g + (size_t)r * HWPIX * 4);
            }
            CP_COMMIT();
        }

        int b = 0;
        for (int k = k0; k < NCHUNK; k += GRID, b ^= 1) {
            CP_WAIT1();              // stage[b] complete (this thread's bytes)
            BAR_SYNC(BAR_FREE(b));   // consumers done with tile[b]

            // binarize stage[b] -> tile[b] (16 rows, 4 px each via LDS.128)
            const float4* st = (const float4*)(smem + b * STAGE_BYTES);
            char* tb = tiles + b * TILE_BYTES;
#pragma unroll
            for (int r = 0; r < 16; r++) {
                float4 v = st[(16 * p + r) * 32 + l];
                uint32_t s0 = setgt(v.x), s1 = setgt(v.y);
                uint32_t s2 = setgt(v.z), s3 = setgt(v.w);
                uint32_t t0 = __byte_perm(s0, s1, 0x0040);
                uint32_t t1 = __byte_perm(s2, s3, 0x0040);
                uint32_t pk = __byte_perm(t0, t1, 0x5410) & 0x01010101u;
                *(uint32_t*)(tb + (uint32_t)(16 * p + r) * TPITCH + 4u * l) = pk;
            }
            MEMBAR_CTA();
            BAR_ARRIVE(BAR_FULL(b)); // tile[b] ready for consumers

            // refill stage[b] with chunk k + 2*GRID
            int kn = k + NSTAGE * GRID;
            if (kn < NCHUNK) {
                const char* g = gbase + (size_t)kn * 512;
                uint32_t d = smem_base + (uint32_t)b * STAGE_BYTES + srow;
#pragma unroll
                for (int r = 0; r < 16; r++)
                    CP_ASYNC16(d + (uint32_t)r * 512u, g + (size_t)r * HWPIX * 4);
            }
            CP_COMMIT();
        }
    } else {
        // ================= CONSUMER =================
        const int cw = w - 8;
        const uint32_t lrow  = (uint32_t)(l & 15);
        const uint32_t lhalf = (uint32_t)((l >> 4) * 16);

        // job tables (two 32x32-tile jobs per warp, <=40 IMMA/chunk)
        static const int J0R[8]  = {0, 1, 2, 3, 0, 0, 0, 1};
        static const int J0C[8]  = {0, 1, 2, 3, 1, 2, 3, 2};
        static const int J0LO[8] = {0, 0, 0, 0, 2, 2, 2, 2};
        static const int J1R[8]  = {0, 0, 0, 1, 1, 1, 2, 2};
        static const int J1C[8]  = {1, 2, 3, 2, 3, 3, 3, 3};
        static const int J1LO[8] = {0, 0, 0, 0, 0, 2, 0, 2};
        static const int J1HI[8] = {2, 2, 2, 2, 2, 4, 2, 4};

        const int  t0r = J0R[cw], t0c = J0C[cw], s0lo = J0LO[cw];
        const int  s0hi = 4;
        const bool d0  = (cw < 4);
        const int  t1r = J1R[cw], t1c = J1C[cw], s1lo = J1LO[cw], s1hi = J1HI[cw];

        int accA[2][4][4], accB[2][4][4];
#pragma unroll
        for (int mi = 0; mi < 2; mi++)
#pragma unroll
            for (int g = 0; g < 4; g++)
#pragma unroll
                for (int e = 0; e < 4; e++) { accA[mi][g][e] = 0; accB[mi][g][e] = 0; }

        // both buffers start "free"
        BAR_ARRIVE(BAR_FREE(0));
        BAR_ARRIVE(BAR_FREE(1));

        int b = 0;
        for (int k = k0; k < NCHUNK; k += GRID, b ^= 1) {
            BAR_SYNC(BAR_FULL(b));   // tile[b] ready
            const uint32_t tbase = smem_u32(tiles + b * TILE_BYTES);
            mma_job(accA, tbase, t0r, t0c, s0lo, s0hi, d0, lrow, lhalf);
            mma_job(accB, tbase, t1r, t1c, s1lo, s1hi, false, lrow, lhalf);
            BAR_ARRIVE(BAR_FREE(b)); // done reading tile[b]
        }

        store_job(accA, t0r, t0c, d0, l);
        store_job(accB, t1r, t1c, false, l);
    }
}

// ---------------------------------------------------------------------------
// Kernel: O(N^2) finish. Gram is upper-triangular: read [min][max].
// ---------------------------------------------------------------------------
__global__ void __launch_bounds__(128, 1)
finish_kernel(const float* __restrict__ boxes,
              const float* __restrict__ scores,
              const int*   __restrict__ labels,
              float*       __restrict__ out) {
    __shared__ float areas[NDET], ssc[NDET];
    __shared__ float x1s[NDET], y1s[NDET], x2s[NDET], y2s[NDET], bareas[NDET];
    __shared__ unsigned char confl[NDET * NDET];
    __shared__ int  ord[NDET];
    __shared__ unsigned char ks[NDET];
    __shared__ unsigned char keepO[NDET];

    const int j = threadIdx.x;

    areas[j] = (float)d_igram[j * NDET + j];
    ssc[j]   = scores[j];
    x1s[j] = boxes[j * 4 + 0];
    y1s[j] = boxes[j * 4 + 1];
    x2s[j] = boxes[j * 4 + 2];
    y2s[j] = boxes[j * 4 + 3];
    __syncthreads();

    const float aj = areas[j];
    for (int i = 0; i < NDET; i++) {
        int lo = (i < j) ? i : j;
        int hi = (i < j) ? j : i;
        float inter = (float)d_igram[lo * NDET + hi];
        float ai    = areas[i];
        float amin  = fminf(ai, aj), amax = fmaxf(ai, aj);
        float iomin = inter / fmaxf(amin, 1.0f);
        float iomax = inter / fmaxf(amax, 1.0f);
        confl[j * NDET + i] = ((iomin > IOMIN_THRESH) || (iomax > IOMAX_THRESH)) ? 1 : 0;
    }

    // stable descending rank
    const float sj = ssc[j];
    int r = 0;
    for (int i = 0; i < NDET; i++) {
        float si = ssc[i];
        r += (si > sj) || (si == sj && i < j);
    }
    ord[r] = j;
    ks[r]  = (aj > MIN_MASK_PIXELS) ? 1 : 0;
    __syncthreads();

    // greedy suppression
    for (int i = 0; i < NDET; i++) {
        bool ki = ks[i];
        if (ki && j > i) {
            if (confl[ord[i] * NDET + ord[j]]) ks[j] = 0;
        }
        __syncthreads();
    }

    // unsort + label filter
    keepO[ord[j]] = ks[j];
    __syncthreads();
    unsigned char kj = (keepO[j] && (labels[j] == PED_LABEL)) ? 1 : 0;
    __syncthreads();
    keepO[j] = kj;
    {
        float wbx = x2s[j] - x1s[j], hbx = y2s[j] - y1s[j];
        bareas[j] = fmaxf(wbx * hbx, 1e-6f);
    }
    __syncthreads();

    // visibility
    const bool high_j = (sj >= HIGH_SCORE_THRESH);
    float cover = 0.0f;
    const float bj = bareas[j];
    for (int i = 0; i < NDET; i++) {
        bool occ = (ssc[i] >= HIGH_SCORE_THRESH) && keepO[i] && (i != j);
        if (occ) {
            float ix1 = fmaxf(x1s[i], x1s[j]);
            float iy1 = fmaxf(y1s[i], y1s[j]);
            float ix2 = fminf(x2s[i], x2s[j]);
            float iy2 = fminf(y2s[i], y2s[j]);
            float bi  = fmaxf(ix2 - ix1, 0.0f) * fmaxf(iy2 - iy1, 0.0f);
            cover = fmaxf(cover, bi / bj);
        }
    }
    float vis = 1.0f - cover;
    bool finalk = keepO[j] && (high_j || (vis < VIS_THRESH));
    out[j] = sj * (finalk ? 1.0f : 0.0f);
}

// ---------------------------------------------------------------------------
// Kernel: zero the gram accumulator for the NEXT invocation (launched last;
// d_igram is statically zero-initialized for the very first call).
// ---------------------------------------------------------------------------
__global__ void zero_gram_kernel() {
    int i = blockIdx.x * blockDim.x + threadIdx.x;
    if (i < GRAMN) d_igram[i] = 0;
}

// ---------------------------------------------------------------------------
// kernel_launch — inputs: boxes f32[128,4], scores f32[128], labels i32[128],
// masks f32[128,1,608,1088]; output f32[128].
// ---------------------------------------------------------------------------
extern "C" void kernel_launch(void* const* d_in, const int* in_sizes, int n_in,
                              void* d_out, int out_size) {
    const float* boxes  = (const float*)d_in[0];
    const float* scores = (const float*)d_in[1];
    const int*   labels = (const int*)d_in[2];
    const float* masks  = (const float*)d_in[3];
    float* out = (float*)d_out;

    static bool attr_set = false;
    if (!attr_set) {
        cudaFuncSetAttribute(gram_kernel,
                             cudaFuncAttributeMaxDynamicSharedMemorySize,
                             SMEM_TOTAL);
        attr_set = true;
    }

    gram_kernel<<<GRID, 512, SMEM_TOTAL>>>(masks);
    finish_kernel<<<1, 128>>>(boxes, scores, labels, out);
    zero_gram_kernel<<<GRAMN / 256, 256>>>();
}

// round 8
// speedup vs baseline: 1.1531x; 1.0545x over previous
#include <cuda_runtime.h>
#include <cstdint>

// ---------------------------------------------------------------------------
// Problem constants
// ---------------------------------------------------------------------------
#define NDET   128
#define HWPIX  661504            // 608 * 1088
#define CHUNKPX 64               // pixels per K-chunk
#define NCHUNK (HWPIX / CHUNKPX) // 10336
#define GRAMN  (NDET * NDET)
#define GRID   148

#define MASK_SCORE_THRESH 0.5f
#define MIN_MASK_PIXELS   20.0f
#define IOMIN_THRESH      0.9f
#define IOMAX_THRESH      0.5f
#define HIGH_SCORE_THRESH 0.5f
#define VIS_THRESH        0.1f
#define PED_LABEL         1

// s8 tile: 128 rows x 64 data bytes, pitch 80 (row offsets mod 128 distinct
// for 8-row groups -> conflict-free ldmatrix)
#define TPITCH 80
#define TILE_BYTES (NDET * TPITCH)        // 10240

// fp32 stage: 128 rows x 256 B, 4-deep
#define STAGE_BYTES (NDET * CHUNKPX * 4)  // 32768
#define NSTAGE 4
#define SMEM_DYN (NSTAGE * STAGE_BYTES + 2 * TILE_BYTES)   // 151552

// Named barrier ids: FULL[tb] = 1+tb, FREE[tb] = 3+tb
#define BAR_FULL(b) (1 + (b))
#define BAR_FREE(b) (3 + (b))

// Global scratch. d_igram upper triangle valid; both re-zeroed by the last
// CTA of each run (statically zero for the very first call).
__device__ int d_igram[GRAMN];
__device__ int d_done;

// ---------------------------------------------------------------------------
// PTX helpers (sm_80+ portable; PTX target is plain sm_100)
// ---------------------------------------------------------------------------
__device__ __forceinline__ uint32_t smem_u32(const void* p) {
    uint32_t a;
    asm("{ .reg .u64 t; cvta.to.shared.u64 t, %1; cvt.u32.u64 %0, t; }"
        : "=r"(a) : "l"(p));
    return a;
}

#define CP_ASYNC16(dst, src)                                               \
    asm volatile("cp.async.cg.shared.global [%0], [%1], 16;"               \
                 :: "r"(dst), "l"(src) : "memory")
#define CP_COMMIT() asm volatile("cp.async.commit_group;" ::: "memory")
#define CP_WAIT3()  asm volatile("cp.async.wait_group 3;" ::: "memory")

#define BAR_SYNC(id)   asm volatile("bar.sync %0, 512;"   :: "r"(id) : "memory")
#define BAR_ARRIVE(id) asm volatile("bar.arrive %0, 512;" :: "r"(id) : "memory")
#define MEMBAR_CTA()   asm volatile("membar.cta;" ::: "memory")

#define LDSM_X4(r0, r1, r2, r3, addr)                                      \
    asm volatile("ldmatrix.sync.aligned.m8n8.x4.shared.b16 "               \
                 "{%0,%1,%2,%3}, [%4];"                                    \
                 : "=r"(r0), "=r"(r1), "=r"(r2), "=r"(r3) : "r"(addr))

#define IMMA16832(c, a0, a1, a2, a3, b0, b1)                               \
    asm volatile("mma.sync.aligned.m16n8k32.row.col.s32.s8.s8.s32 "        \
                 "{%0,%1,%2,%3}, {%4,%5,%6,%7}, {%8,%9}, {%0,%1,%2,%3};"   \
                 : "+r"((c)[0]), "+r"((c)[1]), "+r"((c)[2]), "+r"((c)[3])  \
                 : "r"(a0), "r"(a1), "r"(a2), "r"(a3), "r"(b0), "r"(b1))

__device__ __forceinline__ uint32_t setgt(float v) {
    uint32_t s;
    asm("set.gt.u32.f32 %0, %1, %2;" : "=r"(s) : "f"(v), "f"(MASK_SCORE_THRESH));
    return s;
}

// ---------------------------------------------------------------------------
// One 32x32 tile job (trow,tcol), ksteps [s_lo,s_hi). diag skips the 2
// below-diagonal micro-tiles.
// ---------------------------------------------------------------------------
__device__ __forceinline__ void mma_job(int acc[2][4][4], uint32_t tbase,
                                        int trow, int tcol, int s_lo, int s_hi,
                                        bool diag, uint32_t lrow, uint32_t lhalf) {
    const uint32_t abase = tbase + (uint32_t)(trow * 32 + (int)lrow) * TPITCH;
    const uint32_t bbase = tbase + (uint32_t)(tcol * 32 + (int)lrow) * TPITCH;
    for (int s = s_lo; s < s_hi; s++) {
        const uint32_t kb = (uint32_t)(32 * s) + lhalf;
        uint32_t a0, a1, a2, a3, a4, a5, a6, a7;
        LDSM_X4(a0, a1, a2, a3, abase + kb);
        LDSM_X4(a4, a5, a6, a7, abase + 16u * TPITCH + kb);
        uint32_t b0, b1, b2, b3, b4, b5, b6, b7;
        LDSM_X4(b0, b1, b2, b3, bbase + kb);
        LDSM_X4(b4, b5, b6, b7, bbase + 16u * TPITCH + kb);

        IMMA16832(acc[0][0], a0, a1, a2, a3, b0, b2);
        IMMA16832(acc[0][1], a0, a1, a2, a3, b1, b3);
        IMMA16832(acc[0][2], a0, a1, a2, a3, b4, b6);
        IMMA16832(acc[0][3], a0, a1, a2, a3, b5, b7);
        if (!diag) {
            IMMA16832(acc[1][0], a4, a5, a6, a7, b0, b2);
            IMMA16832(acc[1][1], a4, a5, a6, a7, b1, b3);
        }
        IMMA16832(acc[1][2], a4, a5, a6, a7, b4, b6);
        IMMA16832(acc[1][3], a4, a5, a6, a7, b5, b7);
    }
}

__device__ __forceinline__ void store_job(int acc[2][4][4], int trow, int tcol,
                                          bool diag, int l) {
    const int g4 = l >> 2;
    const int i2 = (l & 3) * 2;
#pragma unroll
    for (int mi = 0; mi < 2; mi++) {
#pragma unroll
        for (int g = 0; g < 4; g++) {
            if (diag && mi == 1 && g < 2) continue;
            int row = trow * 32 + 16 * mi + g4;
            int col = tcol * 32 + 8 * g + i2;
            atomicAdd(&d_igram[row * NDET + col],           acc[mi][g][0]);
            atomicAdd(&d_igram[row * NDET + col + 1],       acc[mi][g][1]);
            atomicAdd(&d_igram[(row + 8) * NDET + col],     acc[mi][g][2]);
            atomicAdd(&d_igram[(row + 8) * NDET + col + 1], acc[mi][g][3]);
        }
    }
}

// ---------------------------------------------------------------------------
// Single fused kernel: binarize + upper-tri Gram (warp-specialized, 4-stage
// cp.async pipeline) + last-CTA finish (NMS/visibility) + scratch re-zero.
// ---------------------------------------------------------------------------
__global__ void __launch_bounds__(512, 1)
postfilter_kernel(const float* __restrict__ masks,
                  const float* __restrict__ boxes,
                  const float* __restrict__ scores,
                  const int*   __restrict__ labels,
                  float*       __restrict__ out) {
    extern __shared__ __align__(16) char smem[];
    char* tiles = smem + NSTAGE * STAGE_BYTES;

    const int tid = threadIdx.x;
    const int w   = tid >> 5;
    const int l   = tid & 31;
    const int k0  = blockIdx.x;

    if (w < 8) {
        // ================= PRODUCER (warps 0-7) =================
        // warp p owns rows 16p..16p+15; lane: fl = float4 idx, rh = row parity
        const int p  = w;
        const int fl = l & 15;
        const int rh = l >> 4;
        const char* gbase = (const char*)masks +
                            (size_t)(16 * p + rh) * HWPIX * 4 + (size_t)(16 * fl);
        const uint32_t smem_base = smem_u32(smem);
        const uint32_t srow = (uint32_t)(16 * p + rh) * 256u + (uint32_t)(16 * fl);

        // prologue: fill 4 stages
#pragma unroll
        for (int s = 0; s < NSTAGE; s++) {
            int kk = k0 + s * GRID;
            if (kk < NCHUNK) {
                const char* g = gbase + (size_t)kk * 256;
                uint32_t d = smem_base + (uint32_t)s * STAGE_BYTES + srow;
#pragma unroll
                for (int t = 0; t < 8; t++)
                    CP_ASYNC16(d + (uint32_t)t * 512u, g + (size_t)t * 2 * HWPIX * 4);
            }
            CP_COMMIT();
        }

        int sk = 0, tb = 0;
        for (int k = k0; k < NCHUNK; k += GRID) {
            CP_WAIT3();               // stage[sk] complete (this thread's data)
            BAR_SYNC(BAR_FREE(tb));   // consumers done with tile[tb]

            // binarize stage[sk] -> tile[tb]
            const char* st = smem + sk * STAGE_BYTES;
            char* tp = tiles + tb * TILE_BYTES;
#pragma unroll
            for (int t = 0; t < 8; t++) {
                int row = 16 * p + 2 * t + rh;
                float4 v = *(const float4*)(st + (uint32_t)row * 256u + 16u * fl);
                uint32_t s0 = setgt(v.x), s1 = setgt(v.y);
                uint32_t s2 = setgt(v.z), s3 = setgt(v.w);
                uint32_t t0 = __byte_perm(s0, s1, 0x0040);
                uint32_t t1 = __byte_perm(s2, s3, 0x0040);
                uint32_t pk = __byte_perm(t0, t1, 0x5410) & 0x01010101u;
                *(uint32_t*)(tp + (uint32_t)row * TPITCH + 4u * fl) = pk;
            }
            MEMBAR_CTA();
            BAR_ARRIVE(BAR_FULL(tb)); // tile[tb] ready

            // refill stage[sk] with chunk k + 4*GRID
            int kn = k + NSTAGE * GRID;
            if (kn < NCHUNK) {
                const char* g = gbase + (size_t)kn * 256;
                uint32_t d = smem_base + (uint32_t)sk * STAGE_BYTES + srow;
#pragma unroll
                for (int t = 0; t < 8; t++)
                    CP_ASYNC16(d + (uint32_t)t * 512u, g + (size_t)t * 2 * HWPIX * 4);
            }
            CP_COMMIT();

            sk = (sk + 1) & 3;
            tb ^= 1;
        }
    } else {
        // ================= CONSUMER (warps 8-15) =================
        const int cw = w - 8;
        const uint32_t lrow  = (uint32_t)(l & 15);
        const uint32_t lhalf = (uint32_t)((l >> 4) * 16);

        // Tile jobs: D0-D3 diag full-K (2 steps); O0..O5 off-diag split into
        // per-step halves. 16-20 IMMA per warp per chunk, all 12 halves +
        // 4 diag covered exactly once.
        static const int JAR[8]  = {0, 1, 2, 3, 1, 2, 0, 1};
        static const int JAC[8]  = {0, 1, 2, 3, 3, 3, 3, 3};
        static const int JALO[8] = {0, 0, 0, 0, 0, 0, 1, 1};
        static const int JAHI[8] = {2, 2, 2, 2, 1, 1, 2, 2};
        static const int JBR[8]  = {0, 0, 0, 1, 0, 0, 1, 2};
        static const int JBC[8]  = {1, 2, 3, 2, 1, 2, 2, 3};
        static const int JBLO[8] = {0, 0, 0, 0, 1, 1, 1, 1};
        static const int JBHI[8] = {1, 1, 1, 1, 2, 2, 2, 2};

        const int  tar = JAR[cw], tac = JAC[cw], alo = JALO[cw], ahi = JAHI[cw];
        const bool da  = (cw < 4);
        const int  tbr = JBR[cw], tbc = JBC[cw], blo = JBLO[cw], bhi = JBHI[cw];

        int accA[2][4][4], accB[2][4][4];
#pragma unroll
        for (int mi = 0; mi < 2; mi++)
#pragma unroll
            for (int g = 0; g < 4; g++)
#pragma unroll
                for (int e = 0; e < 4; e++) { accA[mi][g][e] = 0; accB[mi][g][e] = 0; }

        BAR_ARRIVE(BAR_FREE(0));
        BAR_ARRIVE(BAR_FREE(1));

        int tb = 0;
        for (int k = k0; k < NCHUNK; k += GRID) {
            BAR_SYNC(BAR_FULL(tb));
            const uint32_t tbase = smem_u32(tiles + tb * TILE_BYTES);
            mma_job(accA, tbase, tar, tac, alo, ahi, da, lrow, lhalf);
            mma_job(accB, tbase, tbr, tbc, blo, bhi, false, lrow, lhalf);
            BAR_ARRIVE(BAR_FREE(tb));
            tb ^= 1;
        }

        store_job(accA, tar, tac, da, l);
        store_job(accB, tbr, tbc, false, l);
    }

    // ===================== last-CTA finish phase =====================
    __shared__ int s_rank;
    __syncthreads();
    if (tid == 0) {
        __threadfence();
        s_rank = atomicAdd(&d_done, 1);
    }
    __syncthreads();
    if (s_rank != GRID - 1) return;

    // --- O(N^2) finish, run by the last CTA (512 threads; j-work on tid<128)
    __shared__ float areas[NDET], ssc[NDET];
    __shared__ float x1s[NDET], y1s[NDET], x2s[NDET], y2s[NDET], bareas[NDET];
    __shared__ unsigned char confl[NDET * NDET];
    __shared__ int  ord[NDET];
    __shared__ unsigned char ks[NDET];
    __shared__ unsigned char keepO[NDET];

    const int j = tid;   // valid for tid < 128

    if (j < NDET) {
        areas[j] = (float)__ldcg(&d_igram[j * NDET + j]);
        ssc[j]   = scores[j];
        x1s[j] = boxes[j * 4 + 0];
        y1s[j] = boxes[j * 4 + 1];
        x2s[j] = boxes[j * 4 + 2];
        y2s[j] = boxes[j * 4 + 3];
    }
    __syncthreads();

    // conflict matrix: 512 threads, thread t -> row jj = t&127, i-slice t>>7
    {
        int jj = tid & 127;
        int i0 = (tid >> 7) * 32;
        float aj = areas[jj];
        for (int i = i0; i < i0 + 32; i++) {
            int lo = (i < jj) ? i : jj;
            int hi = (i < jj) ? jj : i;
            float inter = (float)__ldcg(&d_igram[lo * NDET + hi]);
            float ai    = areas[i];
            float amin  = fminf(ai, aj), amax = fmaxf(ai, aj);
            float iomin = inter / fmaxf(amin, 1.0f);
            float iomax = inter / fmaxf(amax, 1.0f);
            confl[jj * NDET + i] =
                ((iomin > IOMIN_THRESH) || (iomax > IOMAX_THRESH)) ? 1 : 0;
        }
    }
    __syncthreads();

    // re-zero scratch for the next replay (no more d_igram reads below)
    {
#pragma unroll
        for (int i = 0; i < GRAMN / 512; i++)
            d_igram[tid + 512 * i] = 0;
        if (tid == 0) d_done = 0;
    }

    // stable descending rank
    if (j < NDET) {
        const float sj = ssc[j];
        int r = 0;
        for (int i = 0; i < NDET; i++) {
            float si = ssc[i];
            r += (si > sj) || (si == sj && i < j);
        }
        ord[r] = j;
        ks[r]  = (areas[j] > MIN_MASK_PIXELS) ? 1 : 0;
    }
    __syncthreads();

    // greedy suppression (serial over i, parallel over j; all threads sync)
    for (int i = 0; i < NDET; i++) {
        if (j < NDET && j > i) {
            if (ks[i] && confl[ord[i] * NDET + ord[j]]) ks[j] = 0;
        }
        __syncthreads();
    }

    if (j < NDET) keepO[ord[j]] = ks[j];
    __syncthreads();
    if (j < NDET) {
        unsigned char kj = (keepO[j] && (labels[j] == PED_LABEL)) ? 1 : 0;
        __syncwarp();
        keepO[j] = kj;
        float wbx = x2s[j] - x1s[j], hbx = y2s[j] - y1s[j];
        bareas[j] = fmaxf(wbx * hbx, 1e-6f);
    }
    __syncthreads();

    if (j < NDET) {
        const float sj = ssc[j];
        const bool high_j = (sj >= HIGH_SCORE_THRESH);
        float cover = 0.0f;
        const float bj = bareas[j];
        for (int i = 0; i < NDET; i++) {
            bool occ = (ssc[i] >= HIGH_SCORE_THRESH) && keepO[i] && (i != j);
            if (occ) {
                float ix1 = fmaxf(x1s[i], x1s[j]);
                float iy1 = fmaxf(y1s[i], y1s[j]);
                float ix2 = fminf(x2s[i], x2s[j]);
                float iy2 = fminf(y2s[i], y2s[j]);
                float bi  = fmaxf(ix2 - ix1, 0.0f) * fmaxf(iy2 - iy1, 0.0f);
                cover = fmaxf(cover, bi / bj);
            }
        }
        float vis = 1.0f - cover;
        bool finalk = keepO[j] && (high_j || (vis < VIS_THRESH));
        out[j] = sj * (finalk ? 1.0f : 0.0f);
    }
}

// ---------------------------------------------------------------------------
// kernel_launch — inputs: boxes f32[128,4], scores f32[128], labels i32[128],
// masks f32[128,1,608,1088]; output f32[128].
// ---------------------------------------------------------------------------
extern "C" void kernel_launch(void* const* d_in, const int* in_sizes, int n_in,
                              void* d_out, int out_size) {
    const float* boxes  = (const float*)d_in[0];
    const float* scores = (const float*)d_in[1];
    const int*   labels = (const int*)d_in[2];
    const float* masks  = (const float*)d_in[3];
    float* out = (float*)d_out;

    static bool attr_set = false;
    if (!attr_set) {
        cudaFuncSetAttribute(postfilter_kernel,
                             cudaFuncAttributeMaxDynamicSharedMemorySize,
                             SMEM_DYN);
        attr_set = true;
    }

    postfilter_kernel<<<GRID, 512, SMEM_DYN>>>(masks, boxes, scores, labels, out);
}

// round 9
// speedup vs baseline: 1.1935x; 1.0350x over previous
#include <cuda_runtime.h>
#include <cstdint>

// ---------------------------------------------------------------------------
// Problem constants
// ---------------------------------------------------------------------------
#define NDET   128
#define HWPIX  661504            // 608 * 1088
#define NCHUNK (HWPIX / 128)     // 5168 K-chunks of 128 pixels
#define GRAMN  (NDET * NDET)
#define GRID   148

#define MASK_SCORE_THRESH 0.5f
#define MIN_MASK_PIXELS   20.0f
#define IOMIN_THRESH      0.9f
#define IOMAX_THRESH      0.5f
#define HIGH_SCORE_THRESH 0.5f
#define VIS_THRESH        0.1f
#define PED_LABEL         1

// s8 tile row pitch (128 data + 16 pad -> conflict-free ldmatrix)
#define TPITCH 144
#define TILE_BYTES (NDET * TPITCH)      // 18432

// fp32 stage: 128 rows x 512 B, double buffered
#define STAGE_BYTES (NDET * 512)        // 65536
#define NSTAGE 2
#define SMEM_DYN (NSTAGE * STAGE_BYTES + 2 * TILE_BYTES)   // 167936

// Named barrier ids: FULL[b] = 1+b, FREE[b] = 3+b
#define BAR_FULL(b) (1 + (b))
#define BAR_FREE(b) (3 + (b))

// Global scratch. d_igram upper triangle valid; both re-zeroed by the last
// CTA of each run (statically zero for the very first call).
__device__ int d_igram[GRAMN];
__device__ int d_done;

// ---------------------------------------------------------------------------
// PTX helpers (sm_80+ portable; PTX target is plain sm_100)
// ---------------------------------------------------------------------------
__device__ __forceinline__ uint32_t smem_u32(const void* p) {
    uint32_t a;
    asm("{ .reg .u64 t; cvta.to.shared.u64 t, %1; cvt.u32.u64 %0, t; }"
        : "=r"(a) : "l"(p));
    return a;
}

#define CP_ASYNC16(dst, src)                                               \
    asm volatile("cp.async.cg.shared.global [%0], [%1], 16;"               \
                 :: "r"(dst), "l"(src) : "memory")
#define CP_COMMIT() asm volatile("cp.async.commit_group;" ::: "memory")
#define CP_WAIT1()  asm volatile("cp.async.wait_group 1;" ::: "memory")

#define BAR_SYNC(id)   asm volatile("bar.sync %0, 512;"   :: "r"(id) : "memory")
#define BAR_ARRIVE(id) asm volatile("bar.arrive %0, 512;" :: "r"(id) : "memory")
#define MEMBAR_CTA()   asm volatile("membar.cta;" ::: "memory")

#define LDSM_X4(r0, r1, r2, r3, addr)                                      \
    asm volatile("ldmatrix.sync.aligned.m8n8.x4.shared.b16 "               \
                 "{%0,%1,%2,%3}, [%4];"                                    \
                 : "=r"(r0), "=r"(r1), "=r"(r2), "=r"(r3) : "r"(addr))

#define IMMA16832(c, a0, a1, a2, a3, b0, b1)                               \
    asm volatile("mma.sync.aligned.m16n8k32.row.col.s32.s8.s8.s32 "        \
                 "{%0,%1,%2,%3}, {%4,%5,%6,%7}, {%8,%9}, {%0,%1,%2,%3};"   \
                 : "+r"((c)[0]), "+r"((c)[1]), "+r"((c)[2]), "+r"((c)[3])  \
                 : "r"(a0), "r"(a1), "r"(a2), "r"(a3), "r"(b0), "r"(b1))

__device__ __forceinline__ uint32_t setgt(float v) {
    uint32_t s;
    asm("set.gt.u32.f32 %0, %1, %2;" : "=r"(s) : "f"(v), "f"(MASK_SCORE_THRESH));
    return s;
}

// ---------------------------------------------------------------------------
// One 32x32 tile job (trow,tcol), ksteps [s_lo,s_hi). diag skips the 2
// below-diagonal micro-tiles.
// ---------------------------------------------------------------------------
__device__ __forceinline__ void mma_job(int acc[2][4][4], uint32_t tbase,
                                        int trow, int tcol, int s_lo, int s_hi,
                                        bool diag, uint32_t lrow, uint32_t lhalf) {
    const uint32_t abase = tbase + (uint32_t)(trow * 32 + (int)lrow) * TPITCH;
    const uint32_t bbase = tbase + (uint32_t)(tcol * 32 + (int)lrow) * TPITCH;
    for (int s = s_lo; s < s_hi; s++) {
        const uint32_t kb = (uint32_t)(32 * s) + lhalf;
        uint32_t a0, a1, a2, a3, a4, a5, a6, a7;
        LDSM_X4(a0, a1, a2, a3, abase + kb);
        LDSM_X4(a4, a5, a6, a7, abase + 16u * TPITCH + kb);
        uint32_t b0, b1, b2, b3, b4, b5, b6, b7;
        LDSM_X4(b0, b1, b2, b3, bbase + kb);
        LDSM_X4(b4, b5, b6, b7, bbase + 16u * TPITCH + kb);

        IMMA16832(acc[0][0], a0, a1, a2, a3, b0, b2);
        IMMA16832(acc[0][1], a0, a1, a2, a3, b1, b3);
        IMMA16832(acc[0][2], a0, a1, a2, a3, b4, b6);
        IMMA16832(acc[0][3], a0, a1, a2, a3, b5, b7);
        if (!diag) {
            IMMA16832(acc[1][0], a4, a5, a6, a7, b0, b2);
            IMMA16832(acc[1][1], a4, a5, a6, a7, b1, b3);
        }
        IMMA16832(acc[1][2], a4, a5, a6, a7, b4, b6);
        IMMA16832(acc[1][3], a4, a5, a6, a7, b5, b7);
    }
}

__device__ __forceinline__ void store_job(int acc[2][4][4], int trow, int tcol,
                                          bool diag, int l) {
    const int g4 = l >> 2;
    const int i2 = (l & 3) * 2;
#pragma unroll
    for (int mi = 0; mi < 2; mi++) {
#pragma unroll
        for (int g = 0; g < 4; g++) {
            if (diag && mi == 1 && g < 2) continue;
            int row = trow * 32 + 16 * mi + g4;
            int col = tcol * 32 + 8 * g + i2;
            atomicAdd(&d_igram[row * NDET + col],           acc[mi][g][0]);
            atomicAdd(&d_igram[row * NDET + col + 1],       acc[mi][g][1]);
            atomicAdd(&d_igram[(row + 8) * NDET + col],     acc[mi][g][2]);
            atomicAdd(&d_igram[(row + 8) * NDET + col + 1], acc[mi][g][3]);
        }
    }
}

// ---------------------------------------------------------------------------
// Single fused kernel:
//  Phase 1 (all 148 CTAs): warp-specialized binarize + upper-tri Gram.
//    warps 0-7  (producers): cp.async fp32 stage (2-deep, 128-px chunks) ->
//                            binarize -> s8 tile[b] (double buffered)
//    warps 8-15 (consumers): ldmatrix + IMMA on tile[b]
//  Phase 2 (last CTA): O(N^2) NMS / visibility finish + scratch re-zero.
// ---------------------------------------------------------------------------
__global__ void __launch_bounds__(512, 1)
postfilter_kernel(const float* __restrict__ masks,
                  const float* __restrict__ boxes,
                  const float* __restrict__ scores,
                  const int*   __restrict__ labels,
                  float*       __restrict__ out) {
    extern __shared__ __align__(16) char smem[];
    char* tiles = smem + NSTAGE * STAGE_BYTES;

    const int tid = threadIdx.x;
    const int w   = tid >> 5;
    const int l   = tid & 31;
    const int k0  = blockIdx.x;

    if (w < 8) {
        // ================= PRODUCER (warps 0-7) =================
        const int p = w;                       // rows 16p..16p+15
        const char* gbase = (const char*)masks +
                            (size_t)(16 * p) * HWPIX * 4 + (size_t)(16 * l);
        const uint32_t smem_base = smem_u32(smem);
        const uint32_t srow = (uint32_t)(16 * p) * 512u + (uint32_t)(16 * l);

        // prologue: fill both stages
#pragma unroll
        for (int s = 0; s < NSTAGE; s++) {
            int kk = k0 + s * GRID;
            if (kk < NCHUNK) {
                const char* g = gbase + (size_t)kk * 512;
                uint32_t d = smem_base + (uint32_t)s * STAGE_BYTES + srow;
#pragma unroll
                for (int r = 0; r < 16; r++)
                    CP_ASYNC16(d + (uint32_t)r * 512u, g + (size_t)r * HWPIX * 4);
            }
            CP_COMMIT();
        }

        int b = 0;
        for (int k = k0; k < NCHUNK; k += GRID, b ^= 1) {
            CP_WAIT1();              // stage[b] complete (this thread's bytes)
            BAR_SYNC(BAR_FREE(b));   // consumers done with tile[b]

            // binarize stage[b] -> tile[b]
            const float4* st = (const float4*)(smem + b * STAGE_BYTES);
            char* tb = tiles + b * TILE_BYTES;
#pragma unroll
            for (int r = 0; r < 16; r++) {
                float4 v = st[(16 * p + r) * 32 + l];
                uint32_t s0 = setgt(v.x), s1 = setgt(v.y);
                uint32_t s2 = setgt(v.z), s3 = setgt(v.w);
                uint32_t t0 = __byte_perm(s0, s1, 0x0040);
                uint32_t t1 = __byte_perm(s2, s3, 0x0040);
                uint32_t pk = __byte_perm(t0, t1, 0x5410) & 0x01010101u;
                *(uint32_t*)(tb + (uint32_t)(16 * p + r) * TPITCH + 4u * l) = pk;
            }
            MEMBAR_CTA();
            BAR_ARRIVE(BAR_FULL(b)); // tile[b] ready for consumers

            // refill stage[b] with chunk k + 2*GRID
            int kn = k + NSTAGE * GRID;
            if (kn < NCHUNK) {
                const char* g = gbase + (size_t)kn * 512;
                uint32_t d = smem_base + (uint32_t)b * STAGE_BYTES + srow;
#pragma unroll
                for (int r = 0; r < 16; r++)
                    CP_ASYNC16(d + (uint32_t)r * 512u, g + (size_t)r * HWPIX * 4);
            }
            CP_COMMIT();
        }
    } else {
        // ================= CONSUMER (warps 8-15) =================
        const int cw = w - 8;
        const uint32_t lrow  = (uint32_t)(l & 15);
        const uint32_t lhalf = (uint32_t)((l >> 4) * 16);

        // job tables (two 32x32-tile jobs per warp, <=40 IMMA/chunk)
        static const int J0R[8]  = {0, 1, 2, 3, 0, 0, 0, 1};
        static const int J0C[8]  = {0, 1, 2, 3, 1, 2, 3, 2};
        static const int J0LO[8] = {0, 0, 0, 0, 2, 2, 2, 2};
        static const int J1R[8]  = {0, 0, 0, 1, 1, 1, 2, 2};
        static const int J1C[8]  = {1, 2, 3, 2, 3, 3, 3, 3};
        static const int J1LO[8] = {0, 0, 0, 0, 0, 2, 0, 2};
        static const int J1HI[8] = {2, 2, 2, 2, 2, 4, 2, 4};

        const int  t0r = J0R[cw], t0c = J0C[cw], s0lo = J0LO[cw];
        const int  s0hi = 4;
        const bool d0  = (cw < 4);
        const int  t1r = J1R[cw], t1c = J1C[cw], s1lo = J1LO[cw], s1hi = J1HI[cw];

        int accA[2][4][4], accB[2][4][4];
#pragma unroll
        for (int mi = 0; mi < 2; mi++)
#pragma unroll
            for (int g = 0; g < 4; g++)
#pragma unroll
                for (int e = 0; e < 4; e++) { accA[mi][g][e] = 0; accB[mi][g][e] = 0; }

        // both buffers start "free"
        BAR_ARRIVE(BAR_FREE(0));
        BAR_ARRIVE(BAR_FREE(1));

        int b = 0;
        for (int k = k0; k < NCHUNK; k += GRID, b ^= 1) {
            BAR_SYNC(BAR_FULL(b));   // tile[b] ready
            const uint32_t tbase = smem_u32(tiles + b * TILE_BYTES);
            mma_job(accA, tbase, t0r, t0c, s0lo, s0hi, d0, lrow, lhalf);
            mma_job(accB, tbase, t1r, t1c, s1lo, s1hi, false, lrow, lhalf);
            BAR_ARRIVE(BAR_FREE(b)); // done reading tile[b]
        }

        store_job(accA, t0r, t0c, d0, l);
        store_job(accB, t1r, t1c, false, l);
    }

    // ===================== last-CTA finish phase =====================
    __shared__ int s_rank;
    __syncthreads();
    if (tid == 0) {
        __threadfence();
        s_rank = atomicAdd(&d_done, 1);
    }
    __syncthreads();
    if (s_rank != GRID - 1) return;

    // --- O(N^2) finish, run by the last CTA (512 threads; j-work on tid<128)
    __shared__ float areas[NDET], ssc[NDET];
    __shared__ float x1s[NDET], y1s[NDET], x2s[NDET], y2s[NDET], bareas[NDET];
    __shared__ unsigned char confl[NDET * NDET];
    __shared__ int  ord[NDET];
    __shared__ unsigned char ks[NDET];
    __shared__ unsigned char keepO[NDET];

    const int j = tid;   // valid for tid < 128

    if (j < NDET) {
        areas[j] = (float)__ldcg(&d_igram[j * NDET + j]);
        ssc[j]   = scores[j];
        x1s[j] = boxes[j * 4 + 0];
        y1s[j] = boxes[j * 4 + 1];
        x2s[j] = boxes[j * 4 + 2];
        y2s[j] = boxes[j * 4 + 3];
    }
    __syncthreads();

    // conflict matrix: 512 threads, thread t -> row jj = t&127, i-slice t>>7
    {
        int jj = tid & 127;
        int i0 = (tid >> 7) * 32;
        float aj = areas[jj];
        for (int i = i0; i < i0 + 32; i++) {
            int lo = (i < jj) ? i : jj;
            int hi = (i < jj) ? jj : i;
            float inter = (float)__ldcg(&d_igram[lo * NDET + hi]);
            float ai    = areas[i];
            float amin  = fminf(ai, aj), amax = fmaxf(ai, aj);
            float iomin = inter / fmaxf(amin, 1.0f);
            float iomax = inter / fmaxf(amax, 1.0f);
            confl[jj * NDET + i] =
                ((iomin > IOMIN_THRESH) || (iomax > IOMAX_THRESH)) ? 1 : 0;
        }
    }
    __syncthreads();

    // re-zero scratch for the next replay (no more d_igram reads below)
    {
#pragma unroll
        for (int i = 0; i < GRAMN / 512; i++)
            d_igram[tid + 512 * i] = 0;
        if (tid == 0) d_done = 0;
    }

    // stable descending rank
    if (j < NDET) {
        const float sj = ssc[j];
        int r = 0;
        for (int i = 0; i < NDET; i++) {
            float si = ssc[i];
            r += (si > sj) || (si == sj && i < j);
        }
        ord[r] = j;
        ks[r]  = (areas[j] > MIN_MASK_PIXELS) ? 1 : 0;
    }
    __syncthreads();

    // greedy suppression (serial over i, parallel over j; all threads sync)
    for (int i = 0; i < NDET; i++) {
        if (j < NDET && j > i) {
            if (ks[i] && confl[ord[i] * NDET + ord[j]]) ks[j] = 0;
        }
        __syncthreads();
    }

    if (j < NDET) keepO[ord[j]] = ks[j];
    __syncthreads();
    if (j < NDET) {
        unsigned char kj = (keepO[j] && (labels[j] == PED_LABEL)) ? 1 : 0;
        __syncwarp();
        keepO[j] = kj;
        float wbx = x2s[j] - x1s[j], hbx = y2s[j] - y1s[j];
        bareas[j] = fmaxf(wbx * hbx, 1e-6f);
    }
    __syncthreads();

    if (j < NDET) {
        const float sj = ssc[j];
        const bool high_j = (sj >= HIGH_SCORE_THRESH);
        float cover = 0.0f;
        const float bj = bareas[j];
        for (int i = 0; i < NDET; i++) {
            bool occ = (ssc[i] >= HIGH_SCORE_THRESH) && keepO[i] && (i != j);
            if (occ) {
                float ix1 = fmaxf(x1s[i], x1s[j]);
                float iy1 = fmaxf(y1s[i], y1s[j]);
                float ix2 = fminf(x2s[i], x2s[j]);
                float iy2 = fminf(y2s[i], y2s[j]);
                float bi  = fmaxf(ix2 - ix1, 0.0f) * fmaxf(iy2 - iy1, 0.0f);
                cover = fmaxf(cover, bi / bj);
            }
        }
        float vis = 1.0f - cover;
        bool finalk = keepO[j] && (high_j || (vis < VIS_THRESH));
        out[j] = sj * (finalk ? 1.0f : 0.0f);
    }
}

// ---------------------------------------------------------------------------
// kernel_launch — inputs: boxes f32[128,4], scores f32[128], labels i32[128],
// masks f32[128,1,608,1088]; output f32[128].
// ---------------------------------------------------------------------------
extern "C" void kernel_launch(void* const* d_in, const int* in_sizes, int n_in,
                              void* d_out, int out_size) {
    const float* boxes  = (const float*)d_in[0];
    const float* scores = (const float*)d_in[1];
    const int*   labels = (const int*)d_in[2];
    const float* masks  = (const float*)d_in[3];
    float* out = (float*)d_out;

    static bool attr_set = false;
    if (!attr_set) {
        cudaFuncSetAttribute(postfilter_kernel,
                             cudaFuncAttributeMaxDynamicSharedMemorySize,
                             SMEM_DYN);
        attr_set = true;
    }

    postfilter_kernel<<<GRID, 512, SMEM_DYN>>>(masks, boxes, scores, labels, out);
}